// round 11
// baseline (speedup 1.0000x reference)
#include <cuda_runtime.h>

#define BB 16
#define SS 4096
#define HH 768
#define NSL 128                 // slices per batch
#define LL 32                   // rows (positions) per slice
#define NEGV (-1e30f)

// ---------------- scratch (static device globals; no allocation) ----------------
__device__ float g_part[BB * NSL * 9];    // per-slice 3x3 semiring partial products
__device__ float g_nump[BB * NSL];        // numerator partial sums (steps t>=1)
__device__ int   g_mskp[BB * NSL];        // mask partial sums (steps t>=1)
__device__ float g_em0[BB * 3];           // emissions row 0 per batch
__device__ float g_llh[BB];               // per-batch log-likelihood
__device__ unsigned int g_cnt[BB];        // per-batch arrival counters (monotonic, mod 128)
__device__ unsigned int g_bcnt;           // batch-finalize counter (monotonic, mod 16)

__device__ __forceinline__ float lse3(float a, float b, float c) {
    float m = fmaxf(a, fmaxf(b, c));
    return m + __logf(__expf(a - m) + __expf(b - m) + __expf(c - m));
}

// ---------------- single fused kernel: emissions + scan + finalize ----------------
// grid = BB*NSL blocks of 256. Block (b,slice) owns rows [slice*32, slice*32+32).
// Phase 1: warp w computes emissions for its 4 rows; butterfly leaves the sums in
//          EVERY lane -> no smem needed.
// Phase 2a (no barrier): each warp chains its own 4 step matrices lane-redundantly
//          (MUFU cost is per warp instruction, so redundancy is free) + numerator.
// Phase 2b: one barrier; entry-parallel 3-level tree over the 8 warp partials.
// Phase 3: LAST block per batch (monotonic atomic counter, mod-128 check) reduces
//          the 128 slice partials; 16th batch-finalizer writes out[0].
__global__ void __launch_bounds__(256, 5) fused_kernel(const float* __restrict__ x,
                                                       const float* __restrict__ W,
                                                       const float* __restrict__ bias,
                                                       const int*   __restrict__ y,
                                                       const int*   __restrict__ mask,
                                                       const float* __restrict__ trans,
                                                       const float* __restrict__ start_t,
                                                       const float* __restrict__ end_t,
                                                       float* __restrict__ out) {
    __shared__ float wP[8 * 9];
    __shared__ float wN[8];
    __shared__ int   wK[8];
    __shared__ float sM[NSL * 9];
    __shared__ float sN[NSL];
    __shared__ int   sK[NSL];
    __shared__ int   s_flag;

    int b     = blockIdx.x >> 7;
    int slice = blockIdx.x & (NSL - 1);
    int tid   = threadIdx.x;
    int wid   = tid >> 5;
    int lane  = tid & 31;
    int R     = b * SS + slice * LL;        // global row base for this block

    float a0[4], a1[4], a2[4];

    // ---- phase 1: emissions. warp wid computes rows R + wid*4 .. +3 ----
    {
        int row0 = R + wid * 4;
        const float4* x4 = reinterpret_cast<const float4*>(x);
        const float4* w4 = reinterpret_cast<const float4*>(W);

#pragma unroll
        for (int r = 0; r < 4; r++) { a0[r] = 0.f; a1[r] = 0.f; a2[r] = 0.f; }

#pragma unroll
        for (int j = 0; j < 6; j++) {
            int idx = lane + 32 * j;          // 0..191
            float4 w0 = __ldg(w4 + idx);
            float4 w1 = __ldg(w4 + 192 + idx);
            float4 w2 = __ldg(w4 + 384 + idx);
#pragma unroll
            for (int r = 0; r < 4; r++) {
                float4 xv = __ldg(x4 + (size_t)(row0 + r) * (HH / 4) + idx);
                a0[r] = fmaf(xv.x, w0.x, fmaf(xv.y, w0.y, fmaf(xv.z, w0.z, fmaf(xv.w, w0.w, a0[r]))));
                a1[r] = fmaf(xv.x, w1.x, fmaf(xv.y, w1.y, fmaf(xv.z, w1.z, fmaf(xv.w, w1.w, a1[r]))));
                a2[r] = fmaf(xv.x, w2.x, fmaf(xv.y, w2.y, fmaf(xv.z, w2.z, fmaf(xv.w, w2.w, a2[r]))));
            }
        }
        // butterfly: every lane ends with the full row sums
#pragma unroll
        for (int off = 16; off; off >>= 1) {
#pragma unroll
            for (int r = 0; r < 4; r++) {
                a0[r] += __shfl_xor_sync(0xFFFFFFFFu, a0[r], off);
                a1[r] += __shfl_xor_sync(0xFFFFFFFFu, a1[r], off);
                a2[r] += __shfl_xor_sync(0xFFFFFFFFu, a2[r], off);
            }
        }
        float b0 = __ldg(bias + 0), b1 = __ldg(bias + 1), b2 = __ldg(bias + 2);
#pragma unroll
        for (int r = 0; r < 4; r++) { a0[r] += b0; a1[r] += b1; a2[r] += b2; }
    }

    // ---- phase 2a: per-warp scan of its 4 rows (no barrier, lane-redundant) ----
    {
        float tr[9];
#pragma unroll
        for (int i = 0; i < 9; i++) tr[i] = __ldg(trans + i);

        float P[9];
        float nsum = 0.f;
        int   msum = 0;
        int   have = 0;
        int   t0   = R + wid * 4;
        int   s0   = slice * LL + wid * 4;

        if (s0 == 0 && lane == 0) {   // block (b,0), warp 0: record row-0 emissions
            g_em0[b * 3 + 0] = a0[0];
            g_em0[b * 3 + 1] = a1[0];
            g_em0[b * 3 + 2] = a2[0];
        }

#pragma unroll
        for (int r = 0; r < 4; r++) {
            int t = t0 + r;
            if (s0 + r > 0) {
                int mk = mask[t];
                if (mk) {
                    float e0 = a0[r], e1 = a1[r], e2 = a2[r];
                    if (!have) {
#pragma unroll
                        for (int i = 0; i < 3; i++) {
                            P[i * 3 + 0] = tr[i * 3 + 0] + e0;
                            P[i * 3 + 1] = tr[i * 3 + 1] + e1;
                            P[i * 3 + 2] = tr[i * 3 + 2] + e2;
                        }
                        have = 1;
                    } else {
                        float C[9];
#pragma unroll
                        for (int i = 0; i < 3; i++) {
                            C[i * 3 + 0] = lse3(P[i * 3 + 0] + tr[0], P[i * 3 + 1] + tr[3], P[i * 3 + 2] + tr[6]) + e0;
                            C[i * 3 + 1] = lse3(P[i * 3 + 0] + tr[1], P[i * 3 + 1] + tr[4], P[i * 3 + 2] + tr[7]) + e1;
                            C[i * 3 + 2] = lse3(P[i * 3 + 0] + tr[2], P[i * 3 + 1] + tr[5], P[i * 3 + 2] + tr[8]) + e2;
                        }
#pragma unroll
                        for (int i = 0; i < 9; i++) P[i] = C[i];
                    }
                    int yt = y[t], yp = y[t - 1];
                    float ey = (yt == 0) ? e0 : ((yt == 1) ? e1 : e2);
                    nsum += tr[yp * 3 + yt] + ey;
                    msum += 1;
                }
            }
        }
        if (!have) {
#pragma unroll
            for (int i = 0; i < 9; i++) P[i] = NEGV;
            P[0] = 0.f; P[4] = 0.f; P[8] = 0.f;
        }

        if (lane == 0) {
#pragma unroll
            for (int i = 0; i < 9; i++) wP[wid * 9 + i] = P[i];
            wN[wid] = nsum;
            wK[wid] = msum;
        }
    }
    __syncthreads();

    // ---- phase 2b: entry-parallel tree over the 8 warp partials (depth 3) ----
    for (int st = 1; st < 8; st <<= 1) {
        int pairs = 8 / (2 * st);
        int jobs  = pairs * 9;
        float cv = 0.f; int off = 0;
        bool doj = tid < jobs;
        if (doj) {
            int p = tid / 9, e = tid - p * 9;
            int i = e / 3, c = e - i * 3;
            int m = p * 2 * st;
            const float* A  = &wP[m * 9];
            const float* Bm = &wP[(m + st) * 9];
            cv  = lse3(A[i * 3 + 0] + Bm[0 + c],
                       A[i * 3 + 1] + Bm[3 + c],
                       A[i * 3 + 2] + Bm[6 + c]);
            off = m * 9 + e;
        }
        bool dos = tid < pairs;
        float nv = 0.f; int kv = 0;
        if (dos) { int m = tid * 2 * st; nv = wN[m] + wN[m + st]; kv = wK[m] + wK[m + st]; }
        __syncthreads();
        if (doj) wP[off] = cv;
        if (dos) { int m = tid * 2 * st; wN[m] = nv; wK[m] = kv; }
        __syncthreads();
    }

    // ---- publish slice partial + arrival bump (all global writes by tid 0) ----
    if (tid == 0) {
        int pi = b * NSL + slice;
#pragma unroll
        for (int i = 0; i < 9; i++) g_part[pi * 9 + i] = wP[i];
        g_nump[pi] = wN[0];
        g_mskp[pi] = wK[0];
        __threadfence();
        unsigned int old = atomicAdd(&g_cnt[b], 1u);
        s_flag = ((old & (NSL - 1u)) == NSL - 1u) ? 1 : 0; // mod 128 (graph replays)
    }
    __syncthreads();
    if (!s_flag) return;

    // ---- phase 3: last block of batch b finalizes ----
    for (int i = tid; i < NSL * 9; i += 256) sM[i] = __ldcg(&g_part[b * NSL * 9 + i]);
    if (tid < NSL) {
        sN[tid] = __ldcg(&g_nump[b * NSL + tid]);
        sK[tid] = __ldcg(&g_mskp[b * NSL + tid]);
    }
    __syncthreads();

    // entry-parallel tree: depth 7, one lse3 per thread-job per level
    for (int st = 1; st < NSL; st <<= 1) {
        int pairs = NSL / (2 * st);
        int jobs  = pairs * 9;
        float Cv[3]; int off[3]; int cnt = 0;
        for (int j = tid; j < jobs; j += 256) {
            int p = j / 9, e = j - p * 9;
            int i = e / 3, c = e - i * 3;
            int m = p * 2 * st;
            const float* A  = &sM[m * 9];
            const float* Bm = &sM[(m + st) * 9];
            Cv[cnt]  = lse3(A[i * 3 + 0] + Bm[0 + c],
                            A[i * 3 + 1] + Bm[3 + c],
                            A[i * 3 + 2] + Bm[6 + c]);
            off[cnt] = m * 9 + e;
            cnt++;
        }
        bool dos = tid < pairs;
        float nv = 0.f; int kv = 0;
        if (dos) { int m = tid * 2 * st; nv = sN[m] + sN[m + st]; kv = sK[m] + sK[m + st]; }
        __syncthreads();
        for (int q = 0; q < cnt; q++) sM[off[q]] = Cv[q];
        if (dos) { int m = tid * 2 * st; sN[m] = nv; sK[m] = kv; }
        __syncthreads();
    }

    if (tid == 0) {
        int bS = b * SS;
        float e0 = __ldcg(&g_em0[b * 3 + 0]);
        float e1 = __ldcg(&g_em0[b * 3 + 1]);
        float e2 = __ldcg(&g_em0[b * 3 + 2]);
        float p0 = start_t[0] + e0;
        float p1 = start_t[1] + e1;
        float p2 = start_t[2] + e2;

        float af0 = lse3(p0 + sM[0], p1 + sM[3], p2 + sM[6]);
        float af1 = lse3(p0 + sM[1], p1 + sM[4], p2 + sM[7]);
        float af2 = lse3(p0 + sM[2], p1 + sM[5], p2 + sM[8]);
        float denom = lse3(af0 + end_t[0], af1 + end_t[1], af2 + end_t[2]);

        int y0 = y[bS];
        float em0y = (y0 == 0) ? e0 : ((y0 == 1) ? e1 : e2);
        float num  = start_t[y0] + em0y + sN[0];
        int   slen = mask[bS] + sK[0];
        num += end_t[y[bS + slen - 1]];

        g_llh[b] = num - denom;
        __threadfence();
        unsigned int ob = atomicAdd(&g_bcnt, 1u);
        if ((ob & (BB - 1u)) == BB - 1u) {                 // 16th batch-finalizer
            float s = 0.f;
#pragma unroll
            for (int i = 0; i < BB; i++) s += __ldcg(&g_llh[i]);
            out[0] = -s / (float)BB;
        }
    }
}

// ---------------- launch ----------------------------------------------------------
extern "C" void kernel_launch(void* const* d_in, const int* in_sizes, int n_in,
                              void* d_out, int out_size) {
    const float* x     = (const float*)d_in[0];
    const int*   y     = (const int*)  d_in[1];
    const int*   mask  = (const int*)  d_in[2];
    const float* W     = (const float*)d_in[3];
    const float* bias  = (const float*)d_in[4];
    const float* st    = (const float*)d_in[5];
    const float* en    = (const float*)d_in[6];
    const float* trans = (const float*)d_in[7];
    float* out = (float*)d_out;

    fused_kernel<<<BB * NSL, 256>>>(x, W, bias, y, mask, trans, st, en, out);
}